// round 8
// baseline (speedup 1.0000x reference)
#include <cuda_runtime.h>
#include <cuda_bf16.h>
#include <cstdint>

// Problem shape: n=4096, m=32768, d=128
#define N_FIX 4096
#define M_FIX 32768
#define D_FIX 128
#define TOT_TILES 8192          // (4096/128) * (32768/128)
#define CTAS 304
#define TPC 27                  // ceil(8192/304)
#define MARGIN 0.5f
#define INV_N (1.0f / 4096.0f)

#define ROWB 144                // padded smem row stride (bytes): 128B data + 16B pad
#define TILE_SM (128 * ROWB)    // 18432 B

// smem layout (bytes)
#define SM_A     0
#define SM_B0    18432
#define SM_B1    36864
#define SM_LABA  55296
#define SM_LABB0 55808
#define SM_LABB1 56320
#define SM_WSUM  56832          // 16 floats
#define SM_TOTAL 56896

// e4m3 scratch (allocation-free rule: __device__ globals)
__device__ uint8_t g_A8[N_FIX * D_FIX];
__device__ uint8_t g_B8[M_FIX * D_FIX];
__device__ int g_labA[N_FIX];
__device__ int g_labB[M_FIX];

// ---------------------------------------------------------------------------
// Prep: fp32 -> e4m3, label extraction (level 0), out zeroing
// ---------------------------------------------------------------------------
__device__ __forceinline__ uint32_t quant4_e4m3(float4 v) {
    uint16_t lo, hi;
    // cvt e4m3x2: first operand -> high byte, second -> low byte
    asm("cvt.rn.satfinite.e4m3x2.f32 %0, %1, %2;" : "=h"(lo) : "f"(v.y), "f"(v.x));
    asm("cvt.rn.satfinite.e4m3x2.f32 %0, %1, %2;" : "=h"(hi) : "f"(v.w), "f"(v.z));
    return (uint32_t)lo | ((uint32_t)hi << 16);
}

__global__ void prep_kernel(const float4* __restrict__ emb,
                            const long long* __restrict__ labels,
                            const float4* __restrict__ ref,
                            const long long* __restrict__ ref_labels,
                            float* __restrict__ out) {
    int tid = blockIdx.x * blockDim.x + threadIdx.x;
    int stride = gridDim.x * blockDim.x;
    if (tid == 0) out[0] = 0.0f;
    uint32_t* A32 = (uint32_t*)g_A8;
    uint32_t* B32 = (uint32_t*)g_B8;
    for (int i = tid; i < N_FIX * D_FIX / 4; i += stride)
        A32[i] = quant4_e4m3(emb[i]);
    for (int i = tid; i < M_FIX * D_FIX / 4; i += stride)
        B32[i] = quant4_e4m3(ref[i]);
    for (int i = tid; i < N_FIX; i += stride)
        g_labA[i] = (int)labels[(long long)i * 2];
    for (int i = tid; i < M_FIX; i += stride)
        g_labB[i] = (int)ref_labels[(long long)i * 2];
}

// ---------------------------------------------------------------------------
// PTX helpers
// ---------------------------------------------------------------------------
__device__ __forceinline__ uint32_t smem_u32(const void* p) {
    return (uint32_t)__cvta_generic_to_shared(p);
}
__device__ __forceinline__ void cp16(uint32_t saddr, const void* gaddr) {
    asm volatile("cp.async.cg.shared.global [%0], [%1], 16;" :: "r"(saddr), "l"(gaddr));
}
__device__ __forceinline__ void cp_commit() { asm volatile("cp.async.commit_group;"); }
__device__ __forceinline__ void cp_wait0()  { asm volatile("cp.async.wait_group 0;" ::: "memory"); }

__device__ __forceinline__ void ldsm_x4(uint32_t* r, uint32_t addr) {
    asm volatile("ldmatrix.sync.aligned.m8n8.x4.shared.b16 {%0,%1,%2,%3}, [%4];"
                 : "=r"(r[0]), "=r"(r[1]), "=r"(r[2]), "=r"(r[3]) : "r"(addr));
}

__device__ __forceinline__ void mma_e4m3(float* c, const uint32_t* a, uint32_t b0, uint32_t b1) {
    asm volatile(
        "mma.sync.aligned.m16n8k32.row.col.f32.e4m3.e4m3.f32 "
        "{%0,%1,%2,%3}, {%4,%5,%6,%7}, {%8,%9}, {%0,%1,%2,%3};"
        : "+f"(c[0]), "+f"(c[1]), "+f"(c[2]), "+f"(c[3])
        : "r"(a[0]), "r"(a[1]), "r"(a[2]), "r"(a[3]), "r"(b0), "r"(b1));
}

// load a 128x128 fp8 tile (rows of 128B) into padded smem: 1024 x 16B chunks
__device__ __forceinline__ void load_tile(uint32_t sbase, const uint8_t* g, int tid) {
#pragma unroll
    for (int j = 0; j < 2; j++) {
        int idx = tid + j * 512;          // 0..1023
        int r = idx >> 3, c = idx & 7;
        cp16(sbase + r * ROWB + c * 16, g + r * D_FIX + c * 16);
    }
}

// ---------------------------------------------------------------------------
// Persistent e4m3 QMMA kernel: 128x128x128 tiles, A resident, B double-buffered
// 512 threads = 16 warps, warp tile 32x32 (4x4 warp grid)
// ---------------------------------------------------------------------------
__global__ __launch_bounds__(512, 2)
void xbm_f8_kernel(float* __restrict__ out) {
    extern __shared__ char smem[];
    const int tid = threadIdx.x, warp = tid >> 5, lane = tid & 31;
    const uint32_t sbase = smem_u32(smem);
    const int* labA_s = (const int*)(smem + SM_LABA);
    float* wsum = (float*)(smem + SM_WSUM);

    int t0 = blockIdx.x * TPC;
    int t1 = t0 + TPC;
    if (t1 > TOT_TILES) t1 = TOT_TILES;
    if (t0 >= t1) { return; }

    const int wm = (warp & 3) * 32;       // row offset of warp tile
    const int wn = (warp >> 2) * 32;      // col offset of warp tile

    // ldmatrix lane-invariant base addresses (k-step advances +32 bytes)
    // A x4: rows wm+(lane&15), byte chunk (lane>>4)*16
    const uint32_t aBase = sbase + SM_A + (uint32_t)(wm + (lane & 15)) * ROWB
                         + ((lane >> 4) << 4);
    // B x4: rows wn+(lane&7)+8*(lane>>4), byte 16*((lane>>3)&1)
    const uint32_t bLane = (uint32_t)(wn + (lane & 7) + ((lane >> 4) << 3)) * ROWB
                         + (((lane >> 3) & 1) << 4);

    // epilogue label indices for this thread
    const int rowA0 = wm + (lane >> 2);
    const int colB0 = wn + ((lane & 3) << 1);

    // prologue: A(nb0) + labA + B(t0) + labB(t0)
    int cur_nb = t0 >> 8;
    {
        int mb = t0 & 255, buf = t0 & 1;
        load_tile(sbase + SM_A, g_A8 + (size_t)cur_nb * 128 * D_FIX, tid);
        load_tile(sbase + SM_B0 + buf * TILE_SM, g_B8 + (size_t)mb * 128 * D_FIX, tid);
        if (tid < 32) {
            cp16(sbase + SM_LABA + tid * 16, g_labA + cur_nb * 128 + tid * 4);
            cp16(sbase + SM_LABB0 + buf * 512 + tid * 16, g_labB + mb * 128 + tid * 4);
        }
        cp_commit();
    }

    float ts[4] = {0.0f, 0.0f, 0.0f, 0.0f};   // 4 independent chains

    for (int t = t0; t < t1; ++t) {
        cp_wait0();
        __syncthreads();                      // B(t) (+A) visible to all

        if ((t >> 8) != cur_nb) {             // A is stale for this tile: reload now
            cur_nb = t >> 8;
            load_tile(sbase + SM_A, g_A8 + (size_t)cur_nb * 128 * D_FIX, tid);
            if (tid < 32) cp16(sbase + SM_LABA + tid * 16, g_labA + cur_nb * 128 + tid * 4);
            cp_commit();
            cp_wait0();
            __syncthreads();
        }

        const int buf = t & 1;
        const uint32_t bBase = sbase + (buf ? SM_B1 : SM_B0) + bLane;
        const int* labB_s = (const int*)(smem + (buf ? SM_LABB1 : SM_LABB0));

        // prefetch next B while computing (overwrites buf^1 = tile t-1's buffer)
        if (t + 1 < t1) {
            int nmb = (t + 1) & 255, nbuf = (t + 1) & 1;
            load_tile(sbase + SM_B0 + nbuf * TILE_SM, g_B8 + (size_t)nmb * 128 * D_FIX, tid);
            if (tid < 32) cp16(sbase + SM_LABB0 + nbuf * 512 + tid * 16,
                               g_labB + nmb * 128 + tid * 4);
            cp_commit();
        }

        // ---- compute 32x32 warp tile, K=128 (4 k-steps of 32) ----
        float acc[2][4][4];
#pragma unroll
        for (int mi = 0; mi < 2; mi++)
#pragma unroll
            for (int ni = 0; ni < 4; ni++)
#pragma unroll
                for (int k = 0; k < 4; k++) acc[mi][ni][k] = 0.0f;

#pragma unroll
        for (int ks = 0; ks < 4; ks++) {
            const int k0 = ks * 32;            // byte offset
            uint32_t a[2][4], b[2][4];
#pragma unroll
            for (int mi = 0; mi < 2; mi++)
                ldsm_x4(a[mi], aBase + mi * (16 * ROWB) + k0);
#pragma unroll
            for (int p = 0; p < 2; p++)
                ldsm_x4(b[p], bBase + p * (16 * ROWB) + k0);
#pragma unroll
            for (int mi = 0; mi < 2; mi++)
#pragma unroll
                for (int ni = 0; ni < 4; ni++)
                    mma_e4m3(acc[mi][ni], a[mi],
                             b[ni >> 1][(ni & 1) * 2], b[ni >> 1][(ni & 1) * 2 + 1]);
        }

        // ---- epilogue: branchless, 4 independent accumulator chains ----
#pragma unroll
        for (int mi = 0; mi < 2; mi++) {
            const int la0 = labA_s[rowA0 + mi * 16];
            const int la1 = labA_s[rowA0 + mi * 16 + 8];
#pragma unroll
            for (int ni = 0; ni < 4; ni++) {
                const int lb0 = labB_s[colB0 + ni * 8];
                const int lb1 = labB_s[colB0 + ni * 8 + 1];
#pragma unroll
                for (int k = 0; k < 4; k++) {
                    const float s = acc[mi][ni][k];
                    const int lA = (k >> 1) ? la1 : la0;
                    const int lB = (k & 1) ? lb1 : lb0;
                    float v;
                    if (lA == lB) v = fmaxf(1.0f - s, 0.0f);
                    else          v = (s > MARGIN) ? s : 0.0f;
                    ts[k] += v;
                }
            }
        }
    }

    // block reduce + single atomic
    float tsum = (ts[0] + ts[1]) + (ts[2] + ts[3]);
#pragma unroll
    for (int off = 16; off > 0; off >>= 1)
        tsum += __shfl_down_sync(0xFFFFFFFFu, tsum, off);
    if (lane == 0) wsum[warp] = tsum;
    __syncthreads();
    if (tid == 0) {
        float s = 0.0f;
#pragma unroll
        for (int i = 0; i < 16; i++) s += wsum[i];
        atomicAdd(out, s * INV_N);
    }
}

// ---------------------------------------------------------------------------
extern "C" void kernel_launch(void* const* d_in, const int* in_sizes, int n_in,
                              void* d_out, int out_size) {
    const float*     emb        = (const float*)d_in[0];
    const long long* labels     = (const long long*)d_in[1];
    const float*     ref        = (const float*)d_in[2];
    const long long* ref_labels = (const long long*)d_in[3];
    float* out = (float*)d_out;

    cudaFuncSetAttribute(xbm_f8_kernel,
                         cudaFuncAttributeMaxDynamicSharedMemorySize, SM_TOTAL);

    prep_kernel<<<512, 256>>>((const float4*)emb, labels, (const float4*)ref,
                              ref_labels, out);
    xbm_f8_kernel<<<CTAS, 512, SM_TOTAL>>>(out);
}

// round 10
// speedup vs baseline: 1.1477x; 1.1477x over previous
#include <cuda_runtime.h>
#include <cuda_bf16.h>
#include <cstdint>

// Problem shape: n=4096, m=32768, d=128
#define N_FIX 4096
#define M_FIX 32768
#define D_FIX 128
#define TOT_TILES 8192          // 32 nb x 256 mb
#define CTAS 152
#define TPC 54                  // ceil(8192/152)
#define MARGIN 0.5f
#define INV_N (1.0f / 4096.0f)
#define DEPTH 4

#define ROWB 272                // bf16 tile row stride: 256B data + 16B pad
#define TILE_SM (128 * ROWB)    // 34816 B

// smem layout (bytes)
#define SM_A      0                          // 34816
#define SM_B      34816                      // 4 slots x 34816 -> 174080
#define SM_LABA   174080                     // 512
#define SM_LABB   174592                     // 4 x 512 -> 176640
#define SM_MBAR   176640                     // full[4] then consumed[4], 8B each
#define SM_WSUM   176704                     // 8 floats
#define SM_TOTAL  176768

// bf16 scratch (allocation-free rule: __device__ globals)
__device__ __nv_bfloat16 g_A[N_FIX * D_FIX];
__device__ __nv_bfloat16 g_B[M_FIX * D_FIX];
__device__ int g_labA[N_FIX];
__device__ int g_labB[M_FIX];

// ---------------------------------------------------------------------------
// Prep: fp32 -> bf16, label extraction (level 0), out zeroing
// ---------------------------------------------------------------------------
__global__ void prep_kernel(const float4* __restrict__ emb,
                            const long long* __restrict__ labels,
                            const float4* __restrict__ ref,
                            const long long* __restrict__ ref_labels,
                            float* __restrict__ out) {
    int tid = blockIdx.x * blockDim.x + threadIdx.x;
    int stride = gridDim.x * blockDim.x;
    if (tid == 0) out[0] = 0.0f;
    for (int i = tid; i < N_FIX * D_FIX / 4; i += stride) {
        float4 v = emb[i];
        __nv_bfloat162* dst = (__nv_bfloat162*)&g_A[i * 4];
        dst[0] = __floats2bfloat162_rn(v.x, v.y);
        dst[1] = __floats2bfloat162_rn(v.z, v.w);
    }
    for (int i = tid; i < M_FIX * D_FIX / 4; i += stride) {
        float4 v = ref[i];
        __nv_bfloat162* dst = (__nv_bfloat162*)&g_B[i * 4];
        dst[0] = __floats2bfloat162_rn(v.x, v.y);
        dst[1] = __floats2bfloat162_rn(v.z, v.w);
    }
    for (int i = tid; i < N_FIX; i += stride)
        g_labA[i] = (int)labels[(long long)i * 2];
    for (int i = tid; i < M_FIX; i += stride)
        g_labB[i] = (int)ref_labels[(long long)i * 2];
}

// ---------------------------------------------------------------------------
// PTX helpers
// ---------------------------------------------------------------------------
__device__ __forceinline__ uint32_t smem_u32(const void* p) {
    return (uint32_t)__cvta_generic_to_shared(p);
}
__device__ __forceinline__ void cp16(uint32_t saddr, const void* gaddr) {
    asm volatile("cp.async.cg.shared.global [%0], [%1], 16;" :: "r"(saddr), "l"(gaddr));
}
__device__ __forceinline__ void cp_wait_all() {
    asm volatile("cp.async.wait_all;" ::: "memory");
}
__device__ __forceinline__ void mbar_init(uint32_t addr, uint32_t cnt) {
    asm volatile("mbarrier.init.shared.b64 [%0], %1;" :: "r"(addr), "r"(cnt) : "memory");
}
__device__ __forceinline__ void mbar_arrive(uint32_t addr) {
    asm volatile("mbarrier.arrive.release.cta.shared::cta.b64 _, [%0];" :: "r"(addr) : "memory");
}
// .noinc is load-bearing: default variant increments expected count (net-zero).
__device__ __forceinline__ void cp_async_mbar_arrive(uint32_t addr) {
    asm volatile("cp.async.mbarrier.arrive.noinc.shared::cta.b64 [%0];" :: "r"(addr) : "memory");
}
__device__ __forceinline__ void mbar_wait(uint32_t addr, uint32_t parity) {
    asm volatile("{\n\t.reg .pred p;\n\t"
                 "WAIT_%=:\n\t"
                 "mbarrier.try_wait.parity.acquire.cta.shared::cta.b64 p, [%0], %1, 0x989680;\n\t"
                 "@!p bra WAIT_%=;\n\t}"
                 :: "r"(addr), "r"(parity) : "memory");
}

__device__ __forceinline__ void ldsm_x4(uint32_t* r, uint32_t addr) {
    asm volatile("ldmatrix.sync.aligned.m8n8.x4.shared.b16 {%0,%1,%2,%3}, [%4];"
                 : "=r"(r[0]), "=r"(r[1]), "=r"(r[2]), "=r"(r[3]) : "r"(addr));
}
__device__ __forceinline__ void mma_bf16(float* c, const uint32_t* a, uint32_t b0, uint32_t b1) {
    asm volatile(
        "mma.sync.aligned.m16n8k16.row.col.f32.bf16.bf16.f32 "
        "{%0,%1,%2,%3}, {%4,%5,%6,%7}, {%8,%9}, {%0,%1,%2,%3};"
        : "+f"(c[0]), "+f"(c[1]), "+f"(c[2]), "+f"(c[3])
        : "r"(a[0]), "r"(a[1]), "r"(a[2]), "r"(a[3]), "r"(b0), "r"(b1));
}

// ---------------------------------------------------------------------------
// Persistent bf16 kernel, warp-specialized:
//   warps 0-7: consumers, 64x32 warp tiles (2x4 grid) of the 128x128 CTA tile
//   warp 8:    producer, fills 4-deep B-slot ring with cp.async
// No __syncthreads in the steady loop; full/consumed mbarriers per slot.
// ---------------------------------------------------------------------------
__global__ __launch_bounds__(288, 1)
void xbm_bf_kernel(float* __restrict__ out) {
    extern __shared__ char smem[];
    const int tid = threadIdx.x, warp = tid >> 5, lane = tid & 31;
    const uint32_t sbase = smem_u32(smem);
    const int* labA_s = (const int*)(smem + SM_LABA);
    float* wsum = (float*)(smem + SM_WSUM);

    const uint32_t FULL = sbase + SM_MBAR;        // full[s] = FULL + 8s
    const uint32_t CONS = sbase + SM_MBAR + 32;   // consumed[s] = CONS + 8s

    int t0 = blockIdx.x * TPC;
    int t1 = t0 + TPC;
    if (t1 > TOT_TILES) t1 = TOT_TILES;

    if (tid == 0) {
#pragma unroll
        for (int s = 0; s < DEPTH; s++) {
            mbar_init(FULL + 8 * s, 32);     // producer lanes (cp.async-tracked)
            mbar_init(CONS + 8 * s, 256);    // 8 consumer warps x 32
        }
    }
    __syncthreads();

    // consumer geometry (R6-validated)
    const int wm = (warp & 1) * 64;
    const int wn = (warp >> 1) * 32;
    const uint32_t aBase = sbase + SM_A + (uint32_t)(wm + (lane & 15)) * ROWB
                         + ((lane >> 4) << 4);
    const uint32_t bLane = (uint32_t)(wn + (lane & 7) + ((lane >> 4) << 3)) * ROWB
                         + (((lane >> 3) & 1) << 4);
    const int rowA0 = wm + (lane >> 2);
    const int colB0 = wn + ((lane & 3) << 1);

    float ts[4] = {0.0f, 0.0f, 0.0f, 0.0f};
    int la[8];

    int segA = t0;
    while (segA < t1) {
        const int nb = segA >> 8;
        int segB = ((nb + 1) << 8);            // next nb boundary
        if (segB > t1) segB = t1;

        // ---- A + labA load (all 9 warps), then resync ----
        {
            const __nv_bfloat16* gA = g_A + (size_t)nb * 128 * D_FIX;
            for (int idx = tid; idx < 2048; idx += 288) {
                int r = idx >> 4, c = idx & 15;
                cp16(sbase + SM_A + r * ROWB + c * 16, gA + r * D_FIX + c * 8);
            }
            if (tid < 32) cp16(sbase + SM_LABA + tid * 16, g_labA + nb * 128 + tid * 4);
            cp_wait_all();
        }
        __syncthreads();

        if (warp == 8) {
            // ================= producer =================
            for (int t = segA; t < segB; ++t) {
                const int i = t - t0, s = i & 3;
                if (i >= DEPTH)
                    mbar_wait(CONS + 8 * s, (uint32_t)(((i - DEPTH) >> 2) & 1));
                const int mb = t & 255;
                const __nv_bfloat16* gB = g_B + (size_t)mb * 128 * D_FIX;
                const uint32_t slot = sbase + SM_B + s * TILE_SM;
#pragma unroll
                for (int j = 0; j < 64; j++) {
                    int idx = lane + j * 32;          // 0..2047
                    int r = idx >> 4, c = idx & 15;
                    cp16(slot + r * ROWB + c * 16, gB + r * D_FIX + c * 8);
                }
                cp16(sbase + SM_LABB + s * 512 + lane * 16, g_labB + mb * 128 + lane * 4);
                cp_async_mbar_arrive(FULL + 8 * s);
            }
        } else {
            // ================= consumers =================
#pragma unroll
            for (int mi = 0; mi < 4; mi++) {
                la[mi * 2]     = labA_s[rowA0 + mi * 16];
                la[mi * 2 + 1] = labA_s[rowA0 + mi * 16 + 8];
            }
            for (int t = segA; t < segB; ++t) {
                const int i = t - t0, s = i & 3;
                mbar_wait(FULL + 8 * s, (uint32_t)((i >> 2) & 1));

                const uint32_t bBase = sbase + SM_B + s * TILE_SM + bLane;
                const int* labB_s = (const int*)(smem + SM_LABB + s * 512);
                int lb[8];
#pragma unroll
                for (int ni = 0; ni < 4; ni++) {
                    lb[ni * 2]     = labB_s[colB0 + ni * 8];
                    lb[ni * 2 + 1] = labB_s[colB0 + ni * 8 + 1];
                }

                float acc[4][4][4];
#pragma unroll
                for (int mi = 0; mi < 4; mi++)
#pragma unroll
                    for (int ni = 0; ni < 4; ni++)
#pragma unroll
                        for (int k = 0; k < 4; k++) acc[mi][ni][k] = 0.0f;

#pragma unroll
                for (int ks = 0; ks < 8; ks++) {
                    const int k0 = ks * 32;
                    uint32_t a[4][4], b[2][4];
#pragma unroll
                    for (int mi = 0; mi < 4; mi++)
                        ldsm_x4(a[mi], aBase + mi * (16 * ROWB) + k0);
#pragma unroll
                    for (int p = 0; p < 2; p++)
                        ldsm_x4(b[p], bBase + p * (16 * ROWB) + k0);
#pragma unroll
                    for (int mi = 0; mi < 4; mi++)
#pragma unroll
                        for (int ni = 0; ni < 4; ni++)
                            mma_bf16(acc[mi][ni], a[mi],
                                     b[ni >> 1][(ni & 1) * 2], b[ni >> 1][(ni & 1) * 2 + 1]);
                }

                mbar_arrive(CONS + 8 * s);     // slot free; epilogue uses regs only

#pragma unroll
                for (int mi = 0; mi < 4; mi++) {
#pragma unroll
                    for (int ni = 0; ni < 4; ni++) {
#pragma unroll
                        for (int k = 0; k < 4; k++) {
                            const float sv = acc[mi][ni][k];
                            const int lA = la[mi * 2 + (k >> 1)];
                            const int lB = lb[ni * 2 + (k & 1)];
                            float v;
                            if (lA == lB) v = fmaxf(1.0f - sv, 0.0f);
                            else          v = (sv > MARGIN) ? sv : 0.0f;
                            ts[k] += v;
                        }
                    }
                }
            }
        }
        segA = segB;
    }

    // block reduce + single atomic (consumers only carry sums)
    float tsum = (ts[0] + ts[1]) + (ts[2] + ts[3]);
#pragma unroll
    for (int off = 16; off > 0; off >>= 1)
        tsum += __shfl_down_sync(0xFFFFFFFFu, tsum, off);
    if (warp < 8 && lane == 0) wsum[warp] = tsum;
    __syncthreads();
    if (tid == 0) {
        float s = 0.0f;
#pragma unroll
        for (int i = 0; i < 8; i++) s += wsum[i];
        atomicAdd(out, s * INV_N);
    }
}

// ---------------------------------------------------------------------------
extern "C" void kernel_launch(void* const* d_in, const int* in_sizes, int n_in,
                              void* d_out, int out_size) {
    const float*     emb        = (const float*)d_in[0];
    const long long* labels     = (const long long*)d_in[1];
    const float*     ref        = (const float*)d_in[2];
    const long long* ref_labels = (const long long*)d_in[3];
    float* out = (float*)d_out;

    cudaFuncSetAttribute(xbm_bf_kernel,
                         cudaFuncAttributeMaxDynamicSharedMemorySize, SM_TOTAL);

    prep_kernel<<<512, 256>>>((const float4*)emb, labels, (const float4*)ref,
                              ref_labels, out);
    xbm_bf_kernel<<<CTAS, 288, SM_TOTAL>>>(out);
}

// round 11
// speedup vs baseline: 1.1693x; 1.0188x over previous
#include <cuda_runtime.h>
#include <cuda_bf16.h>
#include <cstdint>

// Problem shape: n=4096, m=32768, d=128
#define N_FIX 4096
#define M_FIX 32768
#define D_FIX 128
#define TOT_TILES 8192          // t = mb*32 + nb  (mb: 0..255, nb: 0..31)
#define CTAS 304
#define TPC 27                  // ceil(8192/304)
#define MARGIN 0.5f
#define INV_N (1.0f / 4096.0f)

#define ROWB 272                // padded smem row stride (bytes): 256B data + 16B pad
#define TILE_SM (128 * ROWB)    // 34816 B

// smem layout (bytes)
#define SM_BRES   0             // resident B (ref) tile, bf16
#define SM_A0     34816         // A slot 0
#define SM_A1     69632         // A slot 1
#define SM_LABA0  104448        // 512 B
#define SM_LABA1  104960        // 512 B
#define SM_WSUM   105472        // 16 floats
#define SM_TOTAL  105536

// scratch (allocation-free rule: __device__ globals) — A side only
__device__ __nv_bfloat16 g_A[N_FIX * D_FIX];
__device__ int g_labA[N_FIX];

// ---------------------------------------------------------------------------
// Tiny prep: A fp32 -> bf16, labA extraction, out zeroing  (~3MB traffic)
// ---------------------------------------------------------------------------
__global__ void prep_kernel(const float4* __restrict__ emb,
                            const long long* __restrict__ labels,
                            float* __restrict__ out) {
    int tid = blockIdx.x * blockDim.x + threadIdx.x;
    int stride = gridDim.x * blockDim.x;
    if (tid == 0) out[0] = 0.0f;
    for (int i = tid; i < N_FIX * D_FIX / 4; i += stride) {
        float4 v = emb[i];
        __nv_bfloat162* dst = (__nv_bfloat162*)&g_A[i * 4];
        dst[0] = __floats2bfloat162_rn(v.x, v.y);
        dst[1] = __floats2bfloat162_rn(v.z, v.w);
    }
    for (int i = tid; i < N_FIX; i += stride)
        g_labA[i] = (int)labels[(long long)i * 2];
}

// ---------------------------------------------------------------------------
// PTX helpers
// ---------------------------------------------------------------------------
__device__ __forceinline__ uint32_t smem_u32(const void* p) {
    return (uint32_t)__cvta_generic_to_shared(p);
}
__device__ __forceinline__ void cp16(uint32_t saddr, const void* gaddr) {
    asm volatile("cp.async.cg.shared.global [%0], [%1], 16;" :: "r"(saddr), "l"(gaddr));
}
__device__ __forceinline__ void cp_commit() { asm volatile("cp.async.commit_group;"); }
__device__ __forceinline__ void cp_wait0()  { asm volatile("cp.async.wait_group 0;" ::: "memory"); }

__device__ __forceinline__ void ldsm_x4(uint32_t* r, uint32_t addr) {
    asm volatile("ldmatrix.sync.aligned.m8n8.x4.shared.b16 {%0,%1,%2,%3}, [%4];"
                 : "=r"(r[0]), "=r"(r[1]), "=r"(r[2]), "=r"(r[3]) : "r"(addr));
}
__device__ __forceinline__ void mma_bf16(float* c, const uint32_t* a, uint32_t b0, uint32_t b1) {
    asm volatile(
        "mma.sync.aligned.m16n8k16.row.col.f32.bf16.bf16.f32 "
        "{%0,%1,%2,%3}, {%4,%5,%6,%7}, {%8,%9}, {%0,%1,%2,%3};"
        : "+f"(c[0]), "+f"(c[1]), "+f"(c[2]), "+f"(c[3])
        : "r"(a[0]), "r"(a[1]), "r"(a[2]), "r"(a[3]), "r"(b0), "r"(b1));
}

// load a 128x128 bf16 A tile (rows of 256B) into padded smem: 2048 x 16B chunks
__device__ __forceinline__ void load_tileA(uint32_t sbase, const __nv_bfloat16* g, int tid) {
#pragma unroll
    for (int j = 0; j < 4; j++) {
        int idx = tid + j * 512;          // 0..2047
        int r = idx >> 4, c = idx & 15;
        cp16(sbase + r * ROWB + c * 16, g + r * D_FIX + c * 8);
    }
}

// ---------------------------------------------------------------------------
// Persistent bf16 HMMA kernel, strip-mined: B(ref) resident + converted in-kernel,
// A(emb) double-buffered via cp.async. 512 threads, 16 warps, 32x32 warp tiles.
// ---------------------------------------------------------------------------
__global__ __launch_bounds__(512, 2)
void xbm_bf_kernel(float* __restrict__ out,
                   const float4* __restrict__ refB,          // [32768, 32] float4
                   const long long* __restrict__ ref_labels) {
    extern __shared__ char smem[];
    const int tid = threadIdx.x, warp = tid >> 5, lane = tid & 31;
    const uint32_t sbase = smem_u32(smem);
    float* wsum = (float*)(smem + SM_WSUM);

    int t0 = blockIdx.x * TPC;
    int t1 = t0 + TPC;
    if (t1 > TOT_TILES) t1 = TOT_TILES;
    if (t0 >= t1) { return; }

    const int wm = (warp & 3) * 32;       // row offset (A / emb side)
    const int wn = (warp >> 2) * 32;      // col offset (B / ref side)

    // ldmatrix lane-invariant offsets (k-step advances +32 bytes)
    const uint32_t aLane = (uint32_t)(wm + (lane & 15)) * ROWB + ((lane >> 4) << 4);
    const uint32_t bBase = sbase + SM_BRES
                         + (uint32_t)(wn + (lane & 7) + ((lane >> 4) << 3)) * ROWB
                         + (((lane >> 3) & 1) << 4);

    // epilogue label indices for this thread
    const int rowA0 = wm + (lane >> 2);
    const int colB0 = wn + ((lane & 3) << 1);

    // prologue: prefetch A(t0) + its labels
    {
        int nb = t0 & 31, slot = t0 & 1;
        load_tileA(sbase + SM_A0 + slot * TILE_SM, g_A + (size_t)nb * 128 * D_FIX, tid);
        if (tid < 32) cp16(sbase + SM_LABA0 + slot * 512 + tid * 16,
                           g_labA + nb * 128 + tid * 4);
        cp_commit();
    }

    int cur_mb = -1;
    int lb[8];
    float ts[4] = {0.0f, 0.0f, 0.0f, 0.0f};

    for (int t = t0; t < t1; ++t) {
        cp_wait0();
        __syncthreads();                      // A(t) ready; all warps done with tile t-1

        const int mb = t >> 5;
        if (mb != cur_mb) {
            // ---- reload resident B: LDG fp32 -> cvt -> STS (≤2x per CTA) ----
            cur_mb = mb;
            const float4* gB = refB + (size_t)mb * 128 * 32;
#pragma unroll
            for (int j = 0; j < 8; j++) {
                int idx = tid + j * 512;      // 0..4095 float4 chunks
                int r = idx >> 5, c4 = idx & 31;
                float4 v = gB[r * 32 + c4];
                char* dst = smem + SM_BRES + r * ROWB + c4 * 8;
                ((__nv_bfloat162*)dst)[0] = __floats2bfloat162_rn(v.x, v.y);
                ((__nv_bfloat162*)dst)[1] = __floats2bfloat162_rn(v.z, v.w);
            }
            // labB straight to registers
#pragma unroll
            for (int ni = 0; ni < 4; ni++) {
                int col = colB0 + ni * 8;
                lb[ni * 2]     = (int)ref_labels[((long long)mb * 128 + col) * 2];
                lb[ni * 2 + 1] = (int)ref_labels[((long long)mb * 128 + col + 1) * 2];
            }
            __syncthreads();                  // B visible to all warps
        }

        const int slot = t & 1;
        const uint32_t aBase = sbase + SM_A0 + slot * TILE_SM + aLane;
        const int* labA_s = (const int*)(smem + SM_LABA0 + slot * 512);

        // prefetch next A while computing (other slot was freed by the sync above)
        if (t + 1 < t1) {
            int nnb = (t + 1) & 31, nslot = (t + 1) & 1;
            load_tileA(sbase + SM_A0 + nslot * TILE_SM, g_A + (size_t)nnb * 128 * D_FIX, tid);
            if (tid < 32) cp16(sbase + SM_LABA0 + nslot * 512 + tid * 16,
                               g_labA + nnb * 128 + tid * 4);
            cp_commit();
        }

        // ---- compute 32x32 warp tile, K=128 (8 k-steps of 16) ----
        float acc[2][4][4];
#pragma unroll
        for (int mi = 0; mi < 2; mi++)
#pragma unroll
            for (int ni = 0; ni < 4; ni++)
#pragma unroll
                for (int k = 0; k < 4; k++) acc[mi][ni][k] = 0.0f;

#pragma unroll
        for (int ks = 0; ks < 8; ks++) {
            const int k0 = ks * 32;            // byte offset
            uint32_t a[2][4], b[2][4];
#pragma unroll
            for (int mi = 0; mi < 2; mi++)
                ldsm_x4(a[mi], aBase + mi * (16 * ROWB) + k0);
#pragma unroll
            for (int p = 0; p < 2; p++)
                ldsm_x4(b[p], bBase + p * (16 * ROWB) + k0);
#pragma unroll
            for (int mi = 0; mi < 2; mi++)
#pragma unroll
                for (int ni = 0; ni < 4; ni++)
                    mma_bf16(acc[mi][ni], a[mi],
                             b[ni >> 1][(ni & 1) * 2], b[ni >> 1][(ni & 1) * 2 + 1]);
        }

        // ---- epilogue: branchless, 4 independent accumulator chains ----
        const int la0a = labA_s[rowA0];
        const int la0b = labA_s[rowA0 + 8];
        const int la1a = labA_s[rowA0 + 16];
        const int la1b = labA_s[rowA0 + 24];
#pragma unroll
        for (int mi = 0; mi < 2; mi++) {
            const int la0 = mi ? la1a : la0a;
            const int la1 = mi ? la1b : la0b;
#pragma unroll
            for (int ni = 0; ni < 4; ni++) {
                const int lb0 = lb[ni * 2];
                const int lb1 = lb[ni * 2 + 1];
#pragma unroll
                for (int k = 0; k < 4; k++) {
                    const float s = acc[mi][ni][k];
                    const int lA = (k >> 1) ? la1 : la0;
                    const int lB = (k & 1) ? lb1 : lb0;
                    float v;
                    if (lA == lB) v = fmaxf(1.0f - s, 0.0f);
                    else          v = (s > MARGIN) ? s : 0.0f;
                    ts[k] += v;
                }
            }
        }
    }

    // block reduce + single atomic
    float tsum = (ts[0] + ts[1]) + (ts[2] + ts[3]);
#pragma unroll
    for (int off = 16; off > 0; off >>= 1)
        tsum += __shfl_down_sync(0xFFFFFFFFu, tsum, off);
    if (lane == 0) wsum[warp] = tsum;
    __syncthreads();
    if (tid == 0) {
        float s = 0.0f;
#pragma unroll
        for (int i = 0; i < 16; i++) s += wsum[i];
        atomicAdd(out, s * INV_N);
    }
}

// ---------------------------------------------------------------------------
extern "C" void kernel_launch(void* const* d_in, const int* in_sizes, int n_in,
                              void* d_out, int out_size) {
    const float*     emb        = (const float*)d_in[0];
    const long long* labels     = (const long long*)d_in[1];
    const float*     ref        = (const float*)d_in[2];
    const long long* ref_labels = (const long long*)d_in[3];
    float* out = (float*)d_out;

    cudaFuncSetAttribute(xbm_bf_kernel,
                         cudaFuncAttributeMaxDynamicSharedMemorySize, SM_TOTAL);

    prep_kernel<<<128, 256>>>((const float4*)emb, labels, out);
    xbm_bf_kernel<<<CTAS, 512, SM_TOTAL>>>(out, (const float4*)ref, ref_labels);
}

// round 12
// speedup vs baseline: 1.1878x; 1.0158x over previous
#include <cuda_runtime.h>
#include <cuda_fp16.h>
#include <cstdint>

// Problem shape: n=4096, m=32768, d=128
#define N_FIX 4096
#define M_FIX 32768
#define D_FIX 128
#define TOT_TILES 8192          // (4096/128) * (32768/128)
#define CTAS 304
#define TPC 27                  // ceil(8192/304)
#define MARGIN 0.5f
#define INV_N (1.0f / 4096.0f)

#define ROWB 272                // padded smem row stride (bytes): 256B data + 16B pad
#define TILE_SM (128 * ROWB)    // 34816 B

// smem layout (bytes)
#define SM_A     0
#define SM_B0    34816
#define SM_B1    69632
#define SM_LABA  104448
#define SM_LABB0 104960
#define SM_LABB1 105472
#define SM_WSUM  105984         // 16 floats
#define SM_TOTAL 106048

// fp16 scratch (allocation-free rule: __device__ globals)
__device__ __half g_A[N_FIX * D_FIX];
__device__ __half g_B[M_FIX * D_FIX];
__device__ int g_labA[N_FIX];
__device__ int g_labB[M_FIX];

// ---------------------------------------------------------------------------
// Prep: fp32 -> fp16, label extraction (level 0), out zeroing
// ---------------------------------------------------------------------------
__global__ void prep_kernel(const float4* __restrict__ emb,
                            const long long* __restrict__ labels,
                            const float4* __restrict__ ref,
                            const long long* __restrict__ ref_labels,
                            float* __restrict__ out) {
    int tid = blockIdx.x * blockDim.x + threadIdx.x;
    int stride = gridDim.x * blockDim.x;
    if (tid == 0) out[0] = 0.0f;
    for (int i = tid; i < N_FIX * D_FIX / 4; i += stride) {
        float4 v = emb[i];
        __half2* dst = (__half2*)&g_A[i * 4];
        dst[0] = __floats2half2_rn(v.x, v.y);
        dst[1] = __floats2half2_rn(v.z, v.w);
    }
    for (int i = tid; i < M_FIX * D_FIX / 4; i += stride) {
        float4 v = ref[i];
        __half2* dst = (__half2*)&g_B[i * 4];
        dst[0] = __floats2half2_rn(v.x, v.y);
        dst[1] = __floats2half2_rn(v.z, v.w);
    }
    for (int i = tid; i < N_FIX; i += stride)
        g_labA[i] = (int)labels[(long long)i * 2];
    for (int i = tid; i < M_FIX; i += stride)
        g_labB[i] = (int)ref_labels[(long long)i * 2];
}

// ---------------------------------------------------------------------------
// PTX helpers
// ---------------------------------------------------------------------------
__device__ __forceinline__ uint32_t smem_u32(const void* p) {
    return (uint32_t)__cvta_generic_to_shared(p);
}
__device__ __forceinline__ void cp16(uint32_t saddr, const void* gaddr) {
    asm volatile("cp.async.cg.shared.global [%0], [%1], 16;" :: "r"(saddr), "l"(gaddr));
}
__device__ __forceinline__ void cp_commit() { asm volatile("cp.async.commit_group;"); }
__device__ __forceinline__ void cp_wait0()  { asm volatile("cp.async.wait_group 0;" ::: "memory"); }

__device__ __forceinline__ void ldsm_x4(uint32_t* r, uint32_t addr) {
    asm volatile("ldmatrix.sync.aligned.m8n8.x4.shared.b16 {%0,%1,%2,%3}, [%4];"
                 : "=r"(r[0]), "=r"(r[1]), "=r"(r[2]), "=r"(r[3]) : "r"(addr));
}

// f16 inputs, f16 accumulators: C fragment = 2 x f16x2 regs
__device__ __forceinline__ void mma_f16(uint32_t* c, const uint32_t* a, uint32_t b0, uint32_t b1) {
    asm volatile(
        "mma.sync.aligned.m16n8k16.row.col.f16.f16.f16.f16 "
        "{%0,%1}, {%2,%3,%4,%5}, {%6,%7}, {%0,%1};"
        : "+r"(c[0]), "+r"(c[1])
        : "r"(a[0]), "r"(a[1]), "r"(a[2]), "r"(a[3]), "r"(b0), "r"(b1));
}

// load a 128x128 fp16 tile (rows of 256B) into padded smem: 2048 x 16B chunks
__device__ __forceinline__ void load_tile(uint32_t sbase, const __half* g, int tid) {
#pragma unroll
    for (int j = 0; j < 4; j++) {
        int idx = tid + j * 512;          // 0..2047
        int r = idx >> 4, c = idx & 15;
        cp16(sbase + r * ROWB + c * 16, g + r * D_FIX + c * 8);
    }
}

// ---------------------------------------------------------------------------
// Persistent fp16 HMMA kernel: 128x128x128 tiles, A resident, B double-buffered
// 512 threads = 16 warps, warp tile 32x32 (4x4 warp grid), f16 accumulators
// ---------------------------------------------------------------------------
__global__ __launch_bounds__(512, 2)
void xbm_h_kernel(float* __restrict__ out) {
    extern __shared__ char smem[];
    const int tid = threadIdx.x, warp = tid >> 5, lane = tid & 31;
    const uint32_t sbase = smem_u32(smem);
    const int* labA_s = (const int*)(smem + SM_LABA);
    float* wsum = (float*)(smem + SM_WSUM);

    int t0 = blockIdx.x * TPC;
    int t1 = t0 + TPC;
    if (t1 > TOT_TILES) t1 = TOT_TILES;
    if (t0 >= t1) { return; }

    const int wm = (warp & 3) * 32;       // row offset of warp tile
    const int wn = (warp >> 2) * 32;      // col offset of warp tile

    // ldmatrix lane-invariant base addresses (k-step advances +32 bytes)
    const uint32_t aBase = sbase + SM_A + (uint32_t)(wm + (lane & 15)) * ROWB
                         + ((lane >> 4) << 4);
    const uint32_t bLane = (uint32_t)(wn + (lane & 7) + ((lane >> 4) << 3)) * ROWB
                         + (((lane >> 3) & 1) << 4);

    // epilogue label indices for this thread
    const int rowA0 = wm + (lane >> 2);
    const int colB0 = wn + ((lane & 3) << 1);

    // prologue: A(nb0) + labA + B(t0) + labB(t0)
    int cur_nb = t0 >> 8;
    {
        int mb = t0 & 255, buf = t0 & 1;
        load_tile(sbase + SM_A, g_A + (size_t)cur_nb * 128 * D_FIX, tid);
        load_tile(sbase + SM_B0 + buf * TILE_SM, g_B + (size_t)mb * 128 * D_FIX, tid);
        if (tid < 32) {
            cp16(sbase + SM_LABA + tid * 16, g_labA + cur_nb * 128 + tid * 4);
            cp16(sbase + SM_LABB0 + buf * 512 + tid * 16, g_labB + mb * 128 + tid * 4);
        }
        cp_commit();
    }

    float ts[4] = {0.0f, 0.0f, 0.0f, 0.0f};   // 4 independent chains

    for (int t = t0; t < t1; ++t) {
        cp_wait0();
        __syncthreads();                      // B(t) (+A) visible to all

        if ((t >> 8) != cur_nb) {             // A is stale for this tile: reload now
            cur_nb = t >> 8;
            load_tile(sbase + SM_A, g_A + (size_t)cur_nb * 128 * D_FIX, tid);
            if (tid < 32) cp16(sbase + SM_LABA + tid * 16, g_labA + cur_nb * 128 + tid * 4);
            cp_commit();
            cp_wait0();
            __syncthreads();
        }

        const int buf = t & 1;
        const uint32_t bBase = sbase + (buf ? SM_B1 : SM_B0) + bLane;
        const int* labB_s = (const int*)(smem + (buf ? SM_LABB1 : SM_LABB0));

        // prefetch next B while computing (overwrites buf^1 = tile t-1's buffer)
        if (t + 1 < t1) {
            int nmb = (t + 1) & 255, nbuf = (t + 1) & 1;
            load_tile(sbase + SM_B0 + nbuf * TILE_SM, g_B + (size_t)nmb * 128 * D_FIX, tid);
            if (tid < 32) cp16(sbase + SM_LABB0 + nbuf * 512 + tid * 16,
                               g_labB + nmb * 128 + tid * 4);
            cp_commit();
        }

        // ---- compute 32x32 warp tile, K=128 (8 k-steps of 16), f16 acc ----
        uint32_t acc[2][4][2];
#pragma unroll
        for (int mi = 0; mi < 2; mi++)
#pragma unroll
            for (int ni = 0; ni < 4; ni++) {
                acc[mi][ni][0] = 0u; acc[mi][ni][1] = 0u;
            }

#pragma unroll
        for (int ks = 0; ks < 8; ks++) {
            const int k0 = ks * 32;            // byte offset
            uint32_t a[2][4], b[2][4];
#pragma unroll
            for (int mi = 0; mi < 2; mi++)
                ldsm_x4(a[mi], aBase + mi * (16 * ROWB) + k0);
#pragma unroll
            for (int p = 0; p < 2; p++)
                ldsm_x4(b[p], bBase + p * (16 * ROWB) + k0);
#pragma unroll
            for (int mi = 0; mi < 2; mi++)
#pragma unroll
                for (int ni = 0; ni < 4; ni++)
                    mma_f16(acc[mi][ni], a[mi],
                            b[ni >> 1][(ni & 1) * 2], b[ni >> 1][(ni & 1) * 2 + 1]);
        }

        // ---- epilogue: unpack f16x2, branchless, 4 independent chains ----
#pragma unroll
        for (int mi = 0; mi < 2; mi++) {
            const int la0 = labA_s[rowA0 + mi * 16];
            const int la1 = labA_s[rowA0 + mi * 16 + 8];
#pragma unroll
            for (int ni = 0; ni < 4; ni++) {
                const int lb0 = labB_s[colB0 + ni * 8];
                const int lb1 = labB_s[colB0 + ni * 8 + 1];
                const float2 lo = __half22float2(*(const __half2*)&acc[mi][ni][0]);
                const float2 hi = __half22float2(*(const __half2*)&acc[mi][ni][1]);
                const float sv[4] = {lo.x, lo.y, hi.x, hi.y};
#pragma unroll
                for (int k = 0; k < 4; k++) {
                    const float s = sv[k];
                    const int lA = (k >> 1) ? la1 : la0;
                    const int lB = (k & 1) ? lb1 : lb0;
                    float v;
                    if (lA == lB) v = fmaxf(1.0f - s, 0.0f);
                    else          v = (s > MARGIN) ? s : 0.0f;
                    ts[k] += v;
                }
            }
        }
    }

    // block reduce + single atomic
    float tsum = (ts[0] + ts[1]) + (ts[2] + ts[3]);
#pragma unroll
    for (int off = 16; off > 0; off >>= 1)
        tsum += __shfl_down_sync(0xFFFFFFFFu, tsum, off);
    if (lane == 0) wsum[warp] = tsum;
    __syncthreads();
    if (tid == 0) {
        float s = 0.0f;
#pragma unroll
        for (int i = 0; i < 16; i++) s += wsum[i];
        atomicAdd(out, s * INV_N);
    }
}

// ---------------------------------------------------------------------------
extern "C" void kernel_launch(void* const* d_in, const int* in_sizes, int n_in,
                              void* d_out, int out_size) {
    const float*     emb        = (const float*)d_in[0];
    const long long* labels     = (const long long*)d_in[1];
    const float*     ref        = (const float*)d_in[2];
    const long long* ref_labels = (const long long*)d_in[3];
    float* out = (float*)d_out;

    cudaFuncSetAttribute(xbm_h_kernel,
                         cudaFuncAttributeMaxDynamicSharedMemorySize, SM_TOTAL);

    prep_kernel<<<512, 256>>>((const float4*)emb, labels, (const float4*)ref,
                              ref_labels, out);
    xbm_h_kernel<<<CTAS, 512, SM_TOTAL>>>(out);
}